// round 6
// baseline (speedup 1.0000x reference)
#include <cuda_runtime.h>
#include <math.h>
#include <stdint.h>

#define T_INc  128
#define T_OUTc 12
#define LAT    256
#define SQ     140
#define BB     256
#define NROWS  (SQ*BB)      // 35840
#define RBLK   280          // 35840/128

__device__ float g_enc[SQ*BB*LAT];
__device__ float g_gi [T_INc*BB*3*LAT];
__device__ float g_Q  [T_OUTc*BB*LAT];
__device__ float g_h  [BB*LAT];
__device__ float g_pm [T_OUTc*RBLK*BB];
__device__ float g_ps [T_OUTc*RBLK*BB];
__device__ int   g_pidx[T_OUTc*RBLK*BB];
__device__ float g_diag[T_OUTc*BB];
__device__ float g_dll [T_OUTc*BB];
__device__ int   g_corr[T_OUTc*BB];

typedef unsigned long long u64;

#define FMA2(d, a, b) \
    asm("fma.rn.f32x2 %0, %1, %2, %0;" : "+l"(d) : "l"(a), "l"(b))
#define PACK2(out, lo, hi) \
    asm("mov.b64 %0, {%1, %2};" : "=l"(out) : "f"(lo), "f"(hi))
#define UNPACK2(lo, hi, in) \
    asm("mov.b64 {%0, %1}, %2;" : "=f"(lo), "=f"(hi) : "l"(in))

// ---------------------------------------------------------------- conv
__global__ void conv_kernel(const float* __restrict__ X,
                            const float* __restrict__ W,
                            const float* __restrict__ bias) {
    __shared__ float Xs[960];
    const int b = blockIdx.y, t0 = blockIdx.x*20, o = threadIdx.x;
    float w[48];
#pragma unroll
    for (int i = 0; i < 48; i++) w[i] = W[o*48+i];
    const float bb = bias[o];
    const float* xp = X + ((long)b*2048 + (long)t0*4)*12;
    for (int i = threadIdx.x; i < 960; i += 256) Xs[i] = xp[i];
    __syncthreads();
    for (int tt = 0; tt < 20; tt++) {
        float acc = bb;
#pragma unroll
        for (int s = 0; s < 4; s++)
#pragma unroll
            for (int c = 0; c < 12; c++)
                acc += Xs[(tt*4+s)*12+c] * w[c*4+s];
        g_enc[((long)(t0+tt)*BB + b)*LAT + o] = acc;
    }
}

// ------------------------------------------------- packed-f32x2 GEMM tile
// C[m0+128, n0+128] = A[m,:]·Bm[n,:], K=256, both row-major.
// acc2[r][p]: row r, column-pair p (pairs: {tx*4+0,1},{tx*4+2,3},{64+tx*4+0,1},{64+tx*4+2,3})
__device__ __forceinline__ void gemm_tile2(const float* __restrict__ A,
                                           const float* __restrict__ Bm,
                                           int m0, int n0,
                                           u64 acc2[8][4],
                                           float As[16][128], float Bs[16][128]) {
    const int tid = threadIdx.x, tx = tid & 15, ty = tid >> 4;
#pragma unroll
    for (int r = 0; r < 8; r++)
#pragma unroll
        for (int p = 0; p < 4; p++) acc2[r][p] = 0ull;
    for (int kt = 0; kt < 256; kt += 16) {
#pragma unroll
        for (int i = 0; i < 2; i++) {
            int v = tid*2+i, row = v>>2, kk = (v&3)*4;
            float4 a = *(const float4*)(A + (long)(m0+row)*256 + kt + kk);
            As[kk+0][row]=a.x; As[kk+1][row]=a.y; As[kk+2][row]=a.z; As[kk+3][row]=a.w;
            float4 bq = *(const float4*)(Bm + (long)(n0+row)*256 + kt + kk);
            Bs[kk+0][row]=bq.x; Bs[kk+1][row]=bq.y; Bs[kk+2][row]=bq.z; Bs[kk+3][row]=bq.w;
        }
        __syncthreads();
#pragma unroll
        for (int kk = 0; kk < 16; kk++) {
            float a[8];
            *(float4*)(a)   = *(const float4*)&As[kk][ty*4];
            *(float4*)(a+4) = *(const float4*)&As[kk][64+ty*4];
            float4 b0 = *(const float4*)&Bs[kk][tx*4];
            float4 b1 = *(const float4*)&Bs[kk][64+tx*4];
            u64 bp[4];
            PACK2(bp[0], b0.x, b0.y); PACK2(bp[1], b0.z, b0.w);
            PACK2(bp[2], b1.x, b1.y); PACK2(bp[3], b1.z, b1.w);
#pragma unroll
            for (int r = 0; r < 8; r++) {
                u64 av; PACK2(av, a[r], a[r]);
#pragma unroll
                for (int p = 0; p < 4; p++) FMA2(acc2[r][p], av, bp[p]);
            }
        }
        __syncthreads();
    }
}

__device__ __forceinline__ void unpack_acc(const u64 acc2[8][4], float acc[8][8]) {
#pragma unroll
    for (int r = 0; r < 8; r++) {
        UNPACK2(acc[r][0], acc[r][1], acc2[r][0]);
        UNPACK2(acc[r][2], acc[r][3], acc2[r][1]);
        UNPACK2(acc[r][4], acc[r][5], acc2[r][2]);
        UNPACK2(acc[r][6], acc[r][7], acc2[r][3]);
    }
}

__global__ void gemm_bias_kernel(const float* __restrict__ A,
                                 const float* __restrict__ Bm,
                                 const float* __restrict__ bias,
                                 float* __restrict__ C,
                                 int ldA_batch, int ldB_batch, int ldbias_batch,
                                 int ldC_batch, int ncols) {
    __shared__ float As[16][128], Bs[16][128];
    u64 acc2[8][4];
    float acc[8][8];
    const int k = blockIdx.z;
    const int m0 = blockIdx.x*128, n0 = blockIdx.y*128;
    gemm_tile2(A + (long)k*ldA_batch, Bm + (long)k*ldB_batch, m0, n0, acc2, As, Bs);
    unpack_acc(acc2, acc);
    const float* bk = bias + (long)k*ldbias_batch;
    float* Ck = C + (long)k*ldC_batch;
    const int tx = threadIdx.x & 15, ty = threadIdx.x >> 4;
#pragma unroll
    for (int r = 0; r < 8; r++) {
        int grow = m0 + ((r<4) ? ty*4+r : 64+ty*4+(r-4));
#pragma unroll
        for (int h = 0; h < 2; h++) {
            int gc = n0 + (h?64:0) + tx*4;
            float4 v;
            v.x = acc[r][h*4+0]+bk[gc+0]; v.y = acc[r][h*4+1]+bk[gc+1];
            v.z = acc[r][h*4+2]+bk[gc+2]; v.w = acc[r][h*4+3]+bk[gc+3];
            *(float4*)(Ck + (long)grow*ncols + gc) = v;
        }
    }
}

// ---------------------------------------------------------------- GRU
__global__ void gru_kernel(const float* __restrict__ Whh,
                           const float* __restrict__ bhh,
                           float* __restrict__ out) {
    __shared__ float h_s[4][256];
    __shared__ float part[3][4][256];
    const int tid = threadIdx.x, hid = tid & 255, ks = tid >> 8;
    const int b0 = blockIdx.x * 4;
    for (int i = tid; i < 1024; i += 512) ((float*)h_s)[i] = 0.f;
    float bh0=0.f, bh1=0.f, bh2=0.f;
    if (ks == 0) { bh0 = bhh[hid]; bh1 = bhh[256+hid]; bh2 = bhh[512+hid]; }
    __syncthreads();
    const float* W0 = Whh + (long)hid*256;
    const float* W1 = Whh + (long)(256+hid)*256;
    const float* W2 = Whh + (long)(512+hid)*256;
    const int kbase = ks * 128;
    for (int t = 0; t < T_INc; t++) {
        float a0[4]={0,0,0,0}, a1[4]={0,0,0,0}, a2[4]={0,0,0,0};
#pragma unroll 4
        for (int k = kbase; k < kbase+128; k += 4) {
            float4 w0 = *(const float4*)(W0+k);
            float4 w1 = *(const float4*)(W1+k);
            float4 w2 = *(const float4*)(W2+k);
#pragma unroll
            for (int bl = 0; bl < 4; bl++) {
                float4 hv = *(const float4*)&h_s[bl][k];
                a0[bl] += w0.x*hv.x + w0.y*hv.y + w0.z*hv.z + w0.w*hv.w;
                a1[bl] += w1.x*hv.x + w1.y*hv.y + w1.z*hv.z + w1.w*hv.w;
                a2[bl] += w2.x*hv.x + w2.y*hv.y + w2.z*hv.z + w2.w*hv.w;
            }
        }
        if (ks == 1) {
#pragma unroll
            for (int bl = 0; bl < 4; bl++) {
                part[0][bl][hid]=a0[bl]; part[1][bl][hid]=a1[bl]; part[2][bl][hid]=a2[bl];
            }
        }
        __syncthreads();
        if (ks == 0) {
            const float* gi = g_gi + ((long)t*BB + b0)*768;
#pragma unroll
            for (int bl = 0; bl < 4; bl++) {
                float ghr = a0[bl]+part[0][bl][hid]+bh0;
                float ghz = a1[bl]+part[1][bl][hid]+bh1;
                float ghn = a2[bl]+part[2][bl][hid]+bh2;
                float gr = gi[(long)bl*768 + hid]     + ghr;
                float gz = gi[(long)bl*768 + 256+hid] + ghz;
                float gn = gi[(long)bl*768 + 512+hid];
                float r = 1.f/(1.f+expf(-gr));
                float z = 1.f/(1.f+expf(-gz));
                float n = tanhf(gn + r*ghn);
                h_s[bl][hid] = (1.f-z)*n + z*h_s[bl][hid];
            }
        }
        __syncthreads();
    }
    if (ks == 0) {
#pragma unroll
        for (int bl = 0; bl < 4; bl++) {
            int b = b0+bl;
            float hv = h_s[bl][hid];
            g_h[b*256+hid] = hv;
            out[2 + b*256 + hid] = hv;
        }
    }
}

// --------------------------------------------- sim: f32x2 GEMM + fused reduction
__global__ void sim_kernel() {
    __shared__ float As[16][128], Bs[16][128];
    __shared__ float redm[16][128], reds[16][128];
    __shared__ int   redi[16][128];
    __shared__ float colmax[128];
    u64 acc2[8][4];
    float acc[8][8];
    const int rb = blockIdx.x, cb = blockIdx.y, k = blockIdx.z;
    const int m0 = rb*128, n0 = cb*128;
    const int tid = threadIdx.x, tx = tid & 15, ty = tid >> 4;
    gemm_tile2(g_enc, g_Q + (long)k*BB*LAT, m0, n0, acc2, As, Bs);
    unpack_acc(acc2, acc);

    int rl[8], cl[8];
#pragma unroll
    for (int r = 0; r < 8; r++) rl[r] = (r<4) ? ty*4+r : 64+ty*4+(r-4);
#pragma unroll
    for (int c = 0; c < 8; c++) cl[c] = (c<4) ? tx*4+c : 64+tx*4+(c-4);

    const int drow = (T_INc + k) * BB;
#pragma unroll
    for (int j = 0; j < 8; j++) {
        float m = acc[0][j]; int ri = rl[0];
#pragma unroll
        for (int r = 1; r < 8; r++)
            if (acc[r][j] > m) { m = acc[r][j]; ri = rl[r]; }
        redm[ty][cl[j]] = m; redi[ty][cl[j]] = ri;
    }
#pragma unroll
    for (int r = 0; r < 8; r++) {
        int grow = m0 + rl[r];
#pragma unroll
        for (int j = 0; j < 8; j++) {
            int gcol = n0 + cl[j];
            if (grow == drow + gcol) g_diag[k*BB + gcol] = acc[r][j];
        }
    }
    __syncthreads();
    if (tid < 128) {
        float m = redm[0][tid]; int ri = redi[0][tid];
#pragma unroll
        for (int y = 1; y < 16; y++) {
            float v = redm[y][tid]; int vi = redi[y][tid];
            if (v > m || (v == m && vi < ri)) { m = v; ri = vi; }
        }
        colmax[tid] = m;
        long pi = ((long)k*RBLK + rb)*BB + n0 + tid;
        g_pm[pi] = m; g_pidx[pi] = m0 + ri;
    }
    __syncthreads();
#pragma unroll
    for (int j = 0; j < 8; j++) {
        float cm = colmax[cl[j]], s = 0.f;
#pragma unroll
        for (int r = 0; r < 8; r++) s += expf(acc[r][j] - cm);
        reds[ty][cl[j]] = s;
    }
    __syncthreads();
    if (tid < 128) {
        float s = 0.f;
#pragma unroll
        for (int y = 0; y < 16; y++) s += reds[y][tid];
        g_ps[((long)k*RBLK + rb)*BB + n0 + tid] = s;
    }
}

// ---------------------------------------------------------------- combine / finalize
__global__ void combine_kernel() {
    const int k = blockIdx.x, c = threadIdx.x;
    const float* pm = g_pm + (long)k*RBLK*BB;
    const int*  pid = g_pidx + (long)k*RBLK*BB;
    const float* ps = g_ps + (long)k*RBLK*BB;
    float m = pm[c]; int idx = pid[c];
    for (int rb = 1; rb < RBLK; rb++) {
        float v = pm[(long)rb*BB + c];
        if (v > m) { m = v; idx = pid[(long)rb*BB + c]; }
    }
    float s = 0.f;
    for (int rb = 0; rb < RBLK; rb++)
        s += ps[(long)rb*BB + c] * expf(pm[(long)rb*BB + c] - m);
    float lse = m + logf(s);
    g_dll[k*BB + c] = g_diag[k*BB + c] - lse;
    g_corr[k*BB + c] = (idx == BB*(T_INc + k) + c) ? 1 : 0;
}

__global__ void finalize_kernel(float* __restrict__ out) {
    __shared__ float ssum[256];
    __shared__ int scnt[256];
    const int tid = threadIdx.x;
    float s = 0.f; int cnt = 0;
    for (int i = tid; i < T_OUTc*BB; i += 256) { s += g_dll[i]; cnt += g_corr[i]; }
    ssum[tid] = s; scnt[tid] = cnt;
    __syncthreads();
    for (int o = 128; o > 0; o >>= 1) {
        if (tid < o) { ssum[tid] += ssum[tid+o]; scnt[tid] += scnt[tid+o]; }
        __syncthreads();
    }
    if (tid == 0) {
        out[0] = (float)scnt[0] / (float)(T_OUTc*BB);
        out[1] = -ssum[0] / (float)(T_OUTc*BB);
    }
}

extern "C" void kernel_launch(void* const* d_in, const int* in_sizes, int n_in,
                              void* d_out, int out_size) {
    const float* X      = (const float*)d_in[0];
    const float* conv_w = (const float*)d_in[1];
    const float* conv_b = (const float*)d_in[2];
    const float* W_ih   = (const float*)d_in[3];
    const float* W_hh   = (const float*)d_in[4];
    const float* b_ih   = (const float*)d_in[5];
    const float* b_hh   = (const float*)d_in[6];
    const float* pred_W = (const float*)d_in[7];
    const float* pred_b = (const float*)d_in[8];
    float* out = (float*)d_out;

    float* enc_p; cudaGetSymbolAddress((void**)&enc_p, g_enc);
    float* gi_p;  cudaGetSymbolAddress((void**)&gi_p,  g_gi);
    float* h_p;   cudaGetSymbolAddress((void**)&h_p,   g_h);
    float* Q_p;   cudaGetSymbolAddress((void**)&Q_p,   g_Q);

    conv_kernel<<<dim3(7,256), 256>>>(X, conv_w, conv_b);
    gemm_bias_kernel<<<dim3(256,6,1), 256>>>(enc_p, W_ih, b_ih, gi_p, 0,0,0,0, 768);
    gru_kernel<<<64, 512>>>(W_hh, b_hh, out);
    gemm_bias_kernel<<<dim3(2,2,12), 256>>>(h_p, pred_W, pred_b, Q_p,
                                            0, LAT*LAT, LAT, BB*LAT, LAT);
    sim_kernel<<<dim3(RBLK, 2, T_OUTc), 256>>>();
    combine_kernel<<<T_OUTc, 256>>>();
    finalize_kernel<<<1, 256>>>(out);
}

// round 7
// speedup vs baseline: 1.1662x; 1.1662x over previous
#include <cuda_runtime.h>
#include <math.h>
#include <stdint.h>

#define T_INc  128
#define T_OUTc 12
#define LAT    256
#define SQ     140
#define BB     256
#define NROWS  (SQ*BB)      // 35840
#define RBLK   280          // 35840/128

__device__ float g_enc[SQ*BB*LAT];
__device__ float g_gi [T_INc*BB*3*LAT];
__device__ float g_Q  [T_OUTc*BB*LAT];
__device__ float g_h  [BB*LAT];
__device__ float g_pm [T_OUTc*RBLK*BB];
__device__ float g_ps [T_OUTc*RBLK*BB];
__device__ int   g_pidx[T_OUTc*RBLK*BB];
__device__ float g_diag[T_OUTc*BB];
__device__ float g_dll [T_OUTc*BB];
__device__ int   g_corr[T_OUTc*BB];

typedef unsigned long long u64;

#define FMA2(d, a, b) \
    asm("fma.rn.f32x2 %0, %1, %2, %0;" : "+l"(d) : "l"(a), "l"(b))
#define PACK2(out, lo, hi) \
    asm("mov.b64 %0, {%1, %2};" : "=l"(out) : "f"(lo), "f"(hi))
#define UNPACK2(lo, hi, in) \
    asm("mov.b64 {%0, %1}, %2;" : "=f"(lo), "=f"(hi) : "l"(in))

__device__ __forceinline__ float to_tf32(float x) {
    float y;
    asm("cvt.rna.tf32.f32 %0, %1;" : "=f"(y) : "f"(x));
    return y;
}

__device__ __forceinline__ void mma_tf32(float d[4],
                                         const uint32_t a[4],
                                         const uint32_t b[2]) {
    asm volatile(
        "mma.sync.aligned.m16n8k8.row.col.f32.tf32.tf32.f32 "
        "{%0,%1,%2,%3}, {%4,%5,%6,%7}, {%8,%9}, {%0,%1,%2,%3};"
        : "+f"(d[0]), "+f"(d[1]), "+f"(d[2]), "+f"(d[3])
        : "r"(a[0]), "r"(a[1]), "r"(a[2]), "r"(a[3]),
          "r"(b[0]), "r"(b[1]));
}

// ---------------------------------------------------------------- conv
__global__ void conv_kernel(const float* __restrict__ X,
                            const float* __restrict__ W,
                            const float* __restrict__ bias) {
    __shared__ float Xs[960];
    const int b = blockIdx.y, t0 = blockIdx.x*20, o = threadIdx.x;
    float w[48];
#pragma unroll
    for (int i = 0; i < 48; i++) w[i] = W[o*48+i];
    const float bb = bias[o];
    const float* xp = X + ((long)b*2048 + (long)t0*4)*12;
    for (int i = threadIdx.x; i < 960; i += 256) Xs[i] = xp[i];
    __syncthreads();
    for (int tt = 0; tt < 20; tt++) {
        float acc = bb;
#pragma unroll
        for (int s = 0; s < 4; s++)
#pragma unroll
            for (int c = 0; c < 12; c++)
                acc += Xs[(tt*4+s)*12+c] * w[c*4+s];
        g_enc[((long)(t0+tt)*BB + b)*LAT + o] = acc;
    }
}

// ------------------------------------------------- packed-f32x2 fp32 GEMM (GI, Q)
__device__ __forceinline__ void gemm_tile2(const float* __restrict__ A,
                                           const float* __restrict__ Bm,
                                           int m0, int n0,
                                           u64 acc2[8][4],
                                           float As[16][128], float Bs[16][128]) {
    const int tid = threadIdx.x, tx = tid & 15, ty = tid >> 4;
#pragma unroll
    for (int r = 0; r < 8; r++)
#pragma unroll
        for (int p = 0; p < 4; p++) acc2[r][p] = 0ull;
    for (int kt = 0; kt < 256; kt += 16) {
#pragma unroll
        for (int i = 0; i < 2; i++) {
            int v = tid*2+i, row = v>>2, kk = (v&3)*4;
            float4 a = *(const float4*)(A + (long)(m0+row)*256 + kt + kk);
            As[kk+0][row]=a.x; As[kk+1][row]=a.y; As[kk+2][row]=a.z; As[kk+3][row]=a.w;
            float4 bq = *(const float4*)(Bm + (long)(n0+row)*256 + kt + kk);
            Bs[kk+0][row]=bq.x; Bs[kk+1][row]=bq.y; Bs[kk+2][row]=bq.z; Bs[kk+3][row]=bq.w;
        }
        __syncthreads();
#pragma unroll
        for (int kk = 0; kk < 16; kk++) {
            float a[8];
            *(float4*)(a)   = *(const float4*)&As[kk][ty*4];
            *(float4*)(a+4) = *(const float4*)&As[kk][64+ty*4];
            float4 b0 = *(const float4*)&Bs[kk][tx*4];
            float4 b1 = *(const float4*)&Bs[kk][64+tx*4];
            u64 bp[4];
            PACK2(bp[0], b0.x, b0.y); PACK2(bp[1], b0.z, b0.w);
            PACK2(bp[2], b1.x, b1.y); PACK2(bp[3], b1.z, b1.w);
#pragma unroll
            for (int r = 0; r < 8; r++) {
                u64 av; PACK2(av, a[r], a[r]);
#pragma unroll
                for (int p = 0; p < 4; p++) FMA2(acc2[r][p], av, bp[p]);
            }
        }
        __syncthreads();
    }
}

__device__ __forceinline__ void unpack_acc(const u64 acc2[8][4], float acc[8][8]) {
#pragma unroll
    for (int r = 0; r < 8; r++) {
        UNPACK2(acc[r][0], acc[r][1], acc2[r][0]);
        UNPACK2(acc[r][2], acc[r][3], acc2[r][1]);
        UNPACK2(acc[r][4], acc[r][5], acc2[r][2]);
        UNPACK2(acc[r][6], acc[r][7], acc2[r][3]);
    }
}

__global__ void gemm_bias_kernel(const float* __restrict__ A,
                                 const float* __restrict__ Bm,
                                 const float* __restrict__ bias,
                                 float* __restrict__ C,
                                 int ldA_batch, int ldB_batch, int ldbias_batch,
                                 int ldC_batch, int ncols) {
    __shared__ float As[16][128], Bs[16][128];
    u64 acc2[8][4];
    float acc[8][8];
    const int k = blockIdx.z;
    const int m0 = blockIdx.x*128, n0 = blockIdx.y*128;
    gemm_tile2(A + (long)k*ldA_batch, Bm + (long)k*ldB_batch, m0, n0, acc2, As, Bs);
    unpack_acc(acc2, acc);
    const float* bk = bias + (long)k*ldbias_batch;
    float* Ck = C + (long)k*ldC_batch;
    const int tx = threadIdx.x & 15, ty = threadIdx.x >> 4;
#pragma unroll
    for (int r = 0; r < 8; r++) {
        int grow = m0 + ((r<4) ? ty*4+r : 64+ty*4+(r-4));
#pragma unroll
        for (int h = 0; h < 2; h++) {
            int gc = n0 + (h?64:0) + tx*4;
            float4 v;
            v.x = acc[r][h*4+0]+bk[gc+0]; v.y = acc[r][h*4+1]+bk[gc+1];
            v.z = acc[r][h*4+2]+bk[gc+2]; v.w = acc[r][h*4+3]+bk[gc+3];
            *(float4*)(Ck + (long)grow*ncols + gc) = v;
        }
    }
}

// ---------------------------------------------------------------- GRU (128 CTAs x 2 chains)
__global__ void gru_kernel(const float* __restrict__ Whh,
                           const float* __restrict__ bhh,
                           float* __restrict__ out) {
    __shared__ float h_s[2][256];
    __shared__ float part[3][2][256];
    const int tid = threadIdx.x, hid = tid & 255, ks = tid >> 8;
    const int b0 = blockIdx.x * 2;
    for (int i = tid; i < 512; i += 512) ((float*)h_s)[i] = 0.f;
    float bh0=0.f, bh1=0.f, bh2=0.f;
    if (ks == 0) { bh0 = bhh[hid]; bh1 = bhh[256+hid]; bh2 = bhh[512+hid]; }
    __syncthreads();
    const float* W0 = Whh + (long)hid*256;
    const float* W1 = Whh + (long)(256+hid)*256;
    const float* W2 = Whh + (long)(512+hid)*256;
    const int kbase = ks * 128;
    for (int t = 0; t < T_INc; t++) {
        float a0[2]={0,0}, a1[2]={0,0}, a2[2]={0,0};
#pragma unroll 4
        for (int k = kbase; k < kbase+128; k += 4) {
            float4 w0 = *(const float4*)(W0+k);
            float4 w1 = *(const float4*)(W1+k);
            float4 w2 = *(const float4*)(W2+k);
#pragma unroll
            for (int bl = 0; bl < 2; bl++) {
                float4 hv = *(const float4*)&h_s[bl][k];
                a0[bl] += w0.x*hv.x + w0.y*hv.y + w0.z*hv.z + w0.w*hv.w;
                a1[bl] += w1.x*hv.x + w1.y*hv.y + w1.z*hv.z + w1.w*hv.w;
                a2[bl] += w2.x*hv.x + w2.y*hv.y + w2.z*hv.z + w2.w*hv.w;
            }
        }
        if (ks == 1) {
#pragma unroll
            for (int bl = 0; bl < 2; bl++) {
                part[0][bl][hid]=a0[bl]; part[1][bl][hid]=a1[bl]; part[2][bl][hid]=a2[bl];
            }
        }
        __syncthreads();
        if (ks == 0) {
            const float* gi = g_gi + ((long)t*BB + b0)*768;
#pragma unroll
            for (int bl = 0; bl < 2; bl++) {
                float ghr = a0[bl]+part[0][bl][hid]+bh0;
                float ghz = a1[bl]+part[1][bl][hid]+bh1;
                float ghn = a2[bl]+part[2][bl][hid]+bh2;
                float gr = gi[(long)bl*768 + hid]     + ghr;
                float gz = gi[(long)bl*768 + 256+hid] + ghz;
                float gn = gi[(long)bl*768 + 512+hid];
                float r = 1.f/(1.f+expf(-gr));
                float z = 1.f/(1.f+expf(-gz));
                float n = tanhf(gn + r*ghn);
                h_s[bl][hid] = (1.f-z)*n + z*h_s[bl][hid];
            }
        }
        __syncthreads();
    }
    if (ks == 0) {
#pragma unroll
        for (int bl = 0; bl < 2; bl++) {
            int b = b0+bl;
            float hv = h_s[bl][hid];
            g_h[b*256+hid] = hv;
            out[2 + b*256 + hid] = hv;
        }
    }
}

// --------------------------------------- sim: tf32 mma, vectorized fragments
// CTA 128x128xK256; 8 warps (4m x 2n): warp = 32 rows x 64 cols.
// SMEM per k16 chunk: As[128][16], Bs[128][16] row-major (implicit k-perm,
// applied consistently to A and B => product invariant).
__global__ void __launch_bounds__(256) sim_mma_kernel() {
    extern __shared__ float dsm[];
    float* Asf = dsm;                 // [128*16]
    float* Bsf = dsm + 2048;          // [128*16]
    float* slab = dsm;                // [128][130] epilogue, reuses staging

    __shared__ float redm[2][128], reds[2][128], colmax_s[128];
    __shared__ int   redi[2][128];

    const int tid = threadIdx.x, lane = tid & 31, warp = tid >> 5;
    const int wm = (warp & 3) * 32;
    const int wn = (warp >> 2) * 64;
    const int lq = lane & 3, lr = lane >> 2;
    const int rb = blockIdx.x, cb = blockIdx.y, k = blockIdx.z;
    const int m0 = rb*128, n0 = cb*128;
    const float* Ag = g_enc + (size_t)m0*256;
    const float* Bg = g_Q + (size_t)k*BB*LAT + (size_t)n0*256;

    float acc[2][8][4];
#pragma unroll
    for (int mt = 0; mt < 2; mt++)
#pragma unroll
        for (int nt = 0; nt < 8; nt++)
#pragma unroll
            for (int i = 0; i < 4; i++) acc[mt][nt][i] = 0.f;

    for (int kt = 0; kt < 256; kt += 16) {
#pragma unroll
        for (int s = 0; s < 2; s++) {
            int v = tid*2 + s;            // 512 slots: m = v>>2, j = v&3
            int m = v >> 2, j = v & 3;
            float4 av = *(const float4*)(Ag + (size_t)m*256 + kt + j*4);
            av.x = to_tf32(av.x); av.y = to_tf32(av.y);
            av.z = to_tf32(av.z); av.w = to_tf32(av.w);
            *(float4*)(Asf + m*16 + j*4) = av;
            float4 bv = *(const float4*)(Bg + (size_t)m*256 + kt + j*4);
            bv.x = to_tf32(bv.x); bv.y = to_tf32(bv.y);
            bv.z = to_tf32(bv.z); bv.w = to_tf32(bv.w);
            *(float4*)(Bsf + m*16 + j*4) = bv;
        }
        __syncthreads();

        float4 alo[2], ahi[2];
#pragma unroll
        for (int mt = 0; mt < 2; mt++) {
            int mrow = wm + mt*16 + lr;
            alo[mt] = *(const float4*)(Asf + mrow*16 + lq*4);
            ahi[mt] = *(const float4*)(Asf + (mrow+8)*16 + lq*4);
        }
#pragma unroll
        for (int nt = 0; nt < 8; nt++) {
            int nrow = wn + nt*8 + lr;
            float4 bv = *(const float4*)(Bsf + nrow*16 + lq*4);
            uint32_t b0[2] = { __float_as_uint(bv.x), __float_as_uint(bv.y) };
            uint32_t b1[2] = { __float_as_uint(bv.z), __float_as_uint(bv.w) };
#pragma unroll
            for (int mt = 0; mt < 2; mt++) {
                uint32_t a0[4] = { __float_as_uint(alo[mt].x), __float_as_uint(ahi[mt].x),
                                   __float_as_uint(alo[mt].y), __float_as_uint(ahi[mt].y) };
                mma_tf32(acc[mt][nt], a0, b0);
                uint32_t a1[4] = { __float_as_uint(alo[mt].z), __float_as_uint(ahi[mt].z),
                                   __float_as_uint(alo[mt].w), __float_as_uint(ahi[mt].w) };
                mma_tf32(acc[mt][nt], a1, b1);
            }
        }
        __syncthreads();
    }

    // store accums to slab [128][130]
#pragma unroll
    for (int mt = 0; mt < 2; mt++) {
        int r = wm + mt*16 + lr;
#pragma unroll
        for (int nt = 0; nt < 8; nt++) {
            int c = wn + nt*8 + lq*2;
            *(float2*)(slab + (size_t)r*130 + c)     = make_float2(acc[mt][nt][0], acc[mt][nt][1]);
            *(float2*)(slab + (size_t)(r+8)*130 + c) = make_float2(acc[mt][nt][2], acc[mt][nt][3]);
        }
    }
    __syncthreads();

    // column reduction: 256 threads = 2 segments x 128 cols
    const int col = tid & 127, seg = tid >> 7;
    {
        float m = -INFINITY; int ri = 0;
        for (int r = seg*64; r < seg*64 + 64; r++) {
            float v = slab[(size_t)r*130 + col];
            if (v > m) { m = v; ri = r; }
        }
        redm[seg][col] = m; redi[seg][col] = ri;
    }
    __syncthreads();
    if (tid < 128) {
        float m = redm[0][tid]; int ri = redi[0][tid];
        float v = redm[1][tid];
        if (v > m) { m = v; ri = redi[1][tid]; }
        colmax_s[tid] = m;
        long pi = ((long)k*RBLK + rb)*BB + n0 + tid;
        g_pm[pi] = m; g_pidx[pi] = m0 + ri;
        int tr = (T_INc + k)*BB + n0 + tid - m0;   // diag row within tile
        if (tr >= 0 && tr < 128)
            g_diag[k*BB + n0 + tid] = slab[(size_t)tr*130 + tid];
    }
    __syncthreads();
    {
        float cm = colmax_s[col], s = 0.f;
        for (int r = seg*64; r < seg*64 + 64; r++)
            s += expf(slab[(size_t)r*130 + col] - cm);
        reds[seg][col] = s;
    }
    __syncthreads();
    if (tid < 128) {
        long pi = ((long)k*RBLK + rb)*BB + n0 + tid;
        g_ps[pi] = reds[0][tid] + reds[1][tid];
    }
}

// ---------------------------------------------------------------- combine / finalize
__global__ void combine_kernel() {
    const int k = blockIdx.x, c = threadIdx.x;
    const float* pm = g_pm + (long)k*RBLK*BB;
    const int*  pid = g_pidx + (long)k*RBLK*BB;
    const float* ps = g_ps + (long)k*RBLK*BB;
    float m = pm[c]; int idx = pid[c];
    for (int rb = 1; rb < RBLK; rb++) {
        float v = pm[(long)rb*BB + c];
        if (v > m) { m = v; idx = pid[(long)rb*BB + c]; }
    }
    float s = 0.f;
    for (int rb = 0; rb < RBLK; rb++)
        s += ps[(long)rb*BB + c] * expf(pm[(long)rb*BB + c] - m);
    float lse = m + logf(s);
    g_dll[k*BB + c] = g_diag[k*BB + c] - lse;
    g_corr[k*BB + c] = (idx == BB*(T_INc + k) + c) ? 1 : 0;
}

__global__ void finalize_kernel(float* __restrict__ out) {
    __shared__ float ssum[256];
    __shared__ int scnt[256];
    const int tid = threadIdx.x;
    float s = 0.f; int cnt = 0;
    for (int i = tid; i < T_OUTc*BB; i += 256) { s += g_dll[i]; cnt += g_corr[i]; }
    ssum[tid] = s; scnt[tid] = cnt;
    __syncthreads();
    for (int o = 128; o > 0; o >>= 1) {
        if (tid < o) { ssum[tid] += ssum[tid+o]; scnt[tid] += scnt[tid+o]; }
        __syncthreads();
    }
    if (tid == 0) {
        out[0] = (float)scnt[0] / (float)(T_OUTc*BB);
        out[1] = -ssum[0] / (float)(T_OUTc*BB);
    }
}

extern "C" void kernel_launch(void* const* d_in, const int* in_sizes, int n_in,
                              void* d_out, int out_size) {
    const float* X      = (const float*)d_in[0];
    const float* conv_w = (const float*)d_in[1];
    const float* conv_b = (const float*)d_in[2];
    const float* W_ih   = (const float*)d_in[3];
    const float* W_hh   = (const float*)d_in[4];
    const float* b_ih   = (const float*)d_in[5];
    const float* b_hh   = (const float*)d_in[6];
    const float* pred_W = (const float*)d_in[7];
    const float* pred_b = (const float*)d_in[8];
    float* out = (float*)d_out;

    float* enc_p; cudaGetSymbolAddress((void**)&enc_p, g_enc);
    float* gi_p;  cudaGetSymbolAddress((void**)&gi_p,  g_gi);
    float* h_p;   cudaGetSymbolAddress((void**)&h_p,   g_h);
    float* Q_p;   cudaGetSymbolAddress((void**)&Q_p,   g_Q);

    const int SIM_SMEM = 128*130*4;   // 66560 B (slab; staging needs only 16KB)
    cudaFuncSetAttribute(sim_mma_kernel,
                         cudaFuncAttributeMaxDynamicSharedMemorySize, SIM_SMEM);

    conv_kernel<<<dim3(7,256), 256>>>(X, conv_w, conv_b);
    gemm_bias_kernel<<<dim3(256,6,1), 256>>>(enc_p, W_ih, b_ih, gi_p, 0,0,0,0, 768);
    gru_kernel<<<128, 512>>>(W_hh, b_hh, out);
    gemm_bias_kernel<<<dim3(2,2,12), 256>>>(h_p, pred_W, pred_b, Q_p,
                                            0, LAT*LAT, LAT, BB*LAT, LAT);
    sim_mma_kernel<<<dim3(RBLK, 2, T_OUTc), 256, SIM_SMEM>>>();
    combine_kernel<<<T_OUTc, 256>>>();
    finalize_kernel<<<1, 256>>>(out);
}